// round 8
// baseline (speedup 1.0000x reference)
#include <cuda_runtime.h>
#include <cuda_fp16.h>
#include <cstdint>

// LSTM single step, B=64, H=I=O=2048.  out[64,6144] = concat(y, h_new, c_new).
// mma.sync fp16 (fp16 accumulate, dumped to fp32 every K=32).
// Split-K x4: gates 512 CTAs + y 64 CTAs = 576 CTAs x 16 chunks, ~4 CTAs/SM
// to maximize memory-level parallelism on the weight stream.

#define KD 2048
#define NOUT 6144

__device__ __half g_A[64 * 4096];            // concat(h, x) fp16
__device__ float g_part[4][4 * 64 * KD];     // gate partials, 4 K-slices
__device__ float g_yp[2][64 * KD];           // y partials, 2 K-slices

#define SWZ128(o) ((o) ^ (((o) >> 3) & 0x70))

__device__ __forceinline__ uint32_t smem_u32(const void* p) {
    uint32_t a;
    asm("{ .reg .u64 t; cvta.to.shared.u64 t, %1; cvt.u32.u64 %0, t; }"
        : "=r"(a) : "l"(p));
    return a;
}

#define LDSM4(r, addr)                                                       \
    asm volatile("ldmatrix.sync.aligned.m8n8.x4.shared.b16 {%0,%1,%2,%3}, [%4];" \
                 : "=r"((r)[0]), "=r"((r)[1]), "=r"((r)[2]), "=r"((r)[3])    \
                 : "r"(addr))
#define LDSM4T(r, addr)                                                      \
    asm volatile("ldmatrix.sync.aligned.m8n8.x4.trans.shared.b16 {%0,%1,%2,%3}, [%4];" \
                 : "=r"((r)[0]), "=r"((r)[1]), "=r"((r)[2]), "=r"((r)[3])    \
                 : "r"(addr))
#define MMA16816H(d, a, b0, b1)                                              \
    asm volatile("mma.sync.aligned.m16n8k16.row.col.f16.f16.f16.f16 "        \
                 "{%0,%1}, {%2,%3,%4,%5}, {%6,%7}, {%0,%1};"                 \
                 : "+r"((d)[0]), "+r"((d)[1])                                \
                 : "r"((a)[0]), "r"((a)[1]), "r"((a)[2]), "r"((a)[3]),       \
                   "r"(b0), "r"(b1))
#define CP_ASYNC16(saddr, gptr)                                              \
    asm volatile("cp.async.cg.shared.global [%0], [%1], 16;" :: "r"(saddr), "l"(gptr))
#define CP_COMMIT() asm volatile("cp.async.commit_group;" ::: "memory")
#define CP_WAIT1()  asm volatile("cp.async.wait_group 1;" ::: "memory")

// SMEM (relative to 1KB-aligned base):
//   A stages (3): s*8192           (64 rows x 128B fp16)
//   B stages (2): 24576 + s*8192
#define A_OFF(s)  ((uint32_t)(s) * 8192u)
#define B_OFF(s)  (24576u + (uint32_t)(s) * 8192u)
#define SMEM_BYTES (40960 + 1024)

// ---------------------------------------------------------------------------
__global__ void make_A(const float* __restrict__ h, const float* __restrict__ x) {
    int u = blockIdx.x * 256 + threadIdx.x;     // 65536 units of 4 elems
    int idx = u * 4;
    int r = idx >> 12, k = idx & 4095;
    const float* src = (k < 2048) ? (h + r * 2048 + k) : (x + r * 2048 + (k - 2048));
    float4 v = *(const float4*)src;
    __half2 p0 = __floats2half2_rn(v.x, v.y);
    __half2 p1 = __floats2half2_rn(v.z, v.w);
    *(uint2*)(g_A + idx) = make_uint2(*(uint32_t*)&p0, *(uint32_t*)&p1);
}

// ---------------------------------------------------------------------------
// GEMM: 576 CTAs x 16 K-chunks (k64).
//  bx in [0,512): tile=bx>>2 (g=tile>>5, jj=(tile&31)*64), kk=bx&3.
//      half=kk>>1 (0:Wgh,1:Wgx), sub=kk&1; W rows [sub*1024..), A cols kk*1024.
//      Partial -> g_part[kk].
//  bx in [512,576): u=bx-512, jj=(u>>1)*64, kk=u&1; W=Wy rows kk*1024,
//      A cols kk*1024. Partial -> g_yp[kk].
// CTA tile 64(M) x 64(N); 8 warps: mi=w&3 (16 rows), ni=w>>2 (32 cols).
// ---------------------------------------------------------------------------
__global__ void __launch_bounds__(256, 4) gemm_hmma(
    const float* __restrict__ Wfh, const float* __restrict__ Wfx,
    const float* __restrict__ Wih, const float* __restrict__ Wix,
    const float* __restrict__ Wch, const float* __restrict__ Wcx,
    const float* __restrict__ Woh, const float* __restrict__ Wox,
    const float* __restrict__ Wy)
{
    extern __shared__ char smem_raw[];
    uint32_t su0 = smem_u32(smem_raw);
    const uint32_t su = (su0 + 1023u) & ~1023u;
    char* sm = smem_raw + (su - su0);

    const int t = threadIdx.x, bx = blockIdx.x;
    const int lane = t & 31, wid = t >> 5;
    const int mi = wid & 3, ni = wid >> 2;
    const int lr = lane & 15, lc = lane >> 4;

    const float* WH[4] = {Wfh, Wih, Wch, Woh};
    const float* WX[4] = {Wfx, Wix, Wcx, Wox};

    const float* W;
    float* Cout;
    int jj, aCol0, wRow0;
    if (bx < 512) {
        const int tile = bx >> 2, kk = bx & 3;
        const int g = tile >> 5;
        jj = (tile & 31) * 64;
        W = (kk >> 1) ? WX[g] : WH[g];
        wRow0 = (kk & 1) * 1024;
        aCol0 = kk * 1024;
        Cout = g_part[kk] + g * 64 * KD + jj;
    } else {
        const int u = bx - 512, kk = u & 1;
        jj = (u >> 1) * 64;
        W = Wy;
        wRow0 = kk * 1024;
        aCol0 = kk * 1024;
        Cout = g_yp[kk] + jj;
    }

    const int brow = t >> 2, bseg = t & 3;      // B: 64 k-rows x 4 segs

    float master[4][4];
    uint32_t acch[4][2];
#pragma unroll
    for (int j = 0; j < 4; j++) {
#pragma unroll
        for (int q = 0; q < 4; q++) master[j][q] = 0.f;
        acch[j][0] = 0u; acch[j][1] = 0u;
    }

    auto issueA = [&](int c, int s) {
        const int aK = aCol0 + c * 64;
#pragma unroll
        for (int ui = 0; ui < 2; ui++) {
            const int u = t * 2 + ui;
            const int row = u >> 3, cs = u & 7;
            const uint32_t saddr = su + A_OFF(s) + SWZ128(row * 128 + cs * 16);
            const __half* gsrc = g_A + (size_t)row * 4096 + aK + cs * 8;
            CP_ASYNC16(saddr, gsrc);
        }
    };
    auto ldgB = [&](int c, float4* rb) {
        const float* src = W + (size_t)(wRow0 + c * 64 + brow) * 2048 + jj + bseg * 16;
        rb[0] = *(const float4*)(src + 0);
        rb[1] = *(const float4*)(src + 4);
        rb[2] = *(const float4*)(src + 8);
        rb[3] = *(const float4*)(src + 12);
    };

    issueA(0, 0);
    CP_COMMIT();
    float4 rb[4];
    ldgB(0, rb);

    for (int c = 0; c < 16; ++c) {
        const int sa = c % 3, sb = c & 1;

        // Convert + STS B(c) fp32 -> fp16.
        {
            __half2 p[8];
            p[0] = __floats2half2_rn(rb[0].x, rb[0].y);
            p[1] = __floats2half2_rn(rb[0].z, rb[0].w);
            p[2] = __floats2half2_rn(rb[1].x, rb[1].y);
            p[3] = __floats2half2_rn(rb[1].z, rb[1].w);
            p[4] = __floats2half2_rn(rb[2].x, rb[2].y);
            p[5] = __floats2half2_rn(rb[2].z, rb[2].w);
            p[6] = __floats2half2_rn(rb[3].x, rb[3].y);
            p[7] = __floats2half2_rn(rb[3].z, rb[3].w);
            const uint32_t rbse = brow * 128 + bseg * 32;
            *(uint4*)(sm + B_OFF(sb) + SWZ128(rbse)) =
                make_uint4(*(uint32_t*)&p[0], *(uint32_t*)&p[1],
                           *(uint32_t*)&p[2], *(uint32_t*)&p[3]);
            *(uint4*)(sm + B_OFF(sb) + SWZ128(rbse + 16)) =
                make_uint4(*(uint32_t*)&p[4], *(uint32_t*)&p[5],
                           *(uint32_t*)&p[6], *(uint32_t*)&p[7]);
        }

        if (c + 1 < 16) issueA(c + 1, (c + 1) % 3);
        CP_COMMIT();
        CP_WAIT1();           // A(c) resident
        __syncthreads();

        if (c + 1 < 16) ldgB(c + 1, rb);

        // Compute chunk c: 16 fp16-accum MMAs / warp; dump to fp32 every 2 k16.
        {
            const uint32_t aBase = su + A_OFF(sa);
            const uint32_t bBase = su + B_OFF(sb);
#pragma unroll
            for (int ks = 0; ks < 4; ks++) {
                uint32_t a[4];
                LDSM4(a, aBase + SWZ128((mi * 16 + lr) * 128 + ks * 32 + lc * 16));
                const uint32_t brw = (ks * 16 + lr) * 128;
#pragma unroll
                for (int nc = 0; nc < 2; nc++) {
                    uint32_t b[4];
                    LDSM4T(b, bBase + SWZ128(brw + ni * 64 + nc * 32 + lc * 16));
                    MMA16816H(acch[nc*2+0], a, b[0], b[1]);
                    MMA16816H(acch[nc*2+1], a, b[2], b[3]);
                }
                if (ks & 1) {
#pragma unroll
                    for (int g2 = 0; g2 < 4; g2++) {
                        float2 lo = __half22float2(*(__half2*)&acch[g2][0]);
                        float2 hi = __half22float2(*(__half2*)&acch[g2][1]);
                        master[g2][0] += lo.x; master[g2][1] += lo.y;
                        master[g2][2] += hi.x; master[g2][3] += hi.y;
                        acch[g2][0] = 0u; acch[g2][1] = 0u;
                    }
                }
            }
        }
    }

    // Epilogue: raw partial, no bias (fuse adds biases).
    {
        const int m0 = mi * 16 + (lane >> 2);
        const int c2 = (lane & 3) * 2;
#pragma unroll
        for (int j = 0; j < 4; j++) {
            const int n = ni * 32 + j * 8 + c2;
            *(float2*)(Cout + (size_t)m0 * KD + n) =
                make_float2(master[j][0], master[j][1]);
            *(float2*)(Cout + (size_t)(m0 + 8) * KD + n) =
                make_float2(master[j][2], master[j][3]);
        }
    }
}

// ---------------------------------------------------------------------------
// Fuse: sum split-K partials + biases, LSTM pointwise, write y, h, c.
// ---------------------------------------------------------------------------
__global__ void fuse_kernel(const float* __restrict__ c_prev,
                            const float* __restrict__ bf_, const float* __restrict__ bi_,
                            const float* __restrict__ bc_, const float* __restrict__ bo_,
                            const float* __restrict__ by_,
                            float* __restrict__ out) {
    int idx = blockIdx.x * 256 + threadIdx.x;   // 64 * 2048
    int r = idx >> 11, j = idx & 2047;
    float gf = bf_[j], gi = bi_[j], gc = bc_[j], go = bo_[j];
#pragma unroll
    for (int s = 0; s < 4; s++) {
        gf += g_part[s][0 * 64 * KD + idx];
        gi += g_part[s][1 * 64 * KD + idx];
        gc += g_part[s][2 * 64 * KD + idx];
        go += g_part[s][3 * 64 * KD + idx];
    }
    float y = g_yp[0][idx] + g_yp[1][idx] + by_[j];
    float f  = 1.f / (1.f + expf(-gf));
    float ii = 1.f / (1.f + expf(-gi));
    float ct = tanhf(gc);
    float o  = 1.f / (1.f + expf(-go));
    float c  = f * c_prev[idx] + ii * ct;
    float h  = o * tanhf(c);
    out[r * NOUT + j] = y;
    out[r * NOUT + 2048 + j] = h;
    out[r * NOUT + 4096 + j] = c;
}

// ---------------------------------------------------------------------------
extern "C" void kernel_launch(void* const* d_in, const int* in_sizes, int n_in,
                              void* d_out, int out_size) {
    const float* x      = (const float*)d_in[0];
    const float* h_prev = (const float*)d_in[1];
    const float* c_prev = (const float*)d_in[2];
    const float* Wfh = (const float*)d_in[3];
    const float* Wfx = (const float*)d_in[4];
    const float* bf  = (const float*)d_in[5];
    const float* Wih = (const float*)d_in[6];
    const float* Wix = (const float*)d_in[7];
    const float* bi  = (const float*)d_in[8];
    const float* Woh = (const float*)d_in[9];
    const float* Wox = (const float*)d_in[10];
    const float* bo  = (const float*)d_in[11];
    const float* Wch = (const float*)d_in[12];
    const float* Wcx = (const float*)d_in[13];
    const float* bc  = (const float*)d_in[14];
    const float* Wy  = (const float*)d_in[15];
    const float* by  = (const float*)d_in[16];
    float* out = (float*)d_out;

    static int smem_set = 0;
    if (!smem_set) {
        cudaFuncSetAttribute(gemm_hmma, cudaFuncAttributeMaxDynamicSharedMemorySize,
                             SMEM_BYTES);
        smem_set = 1;
    }

    make_A<<<256, 256>>>(h_prev, x);
    gemm_hmma<<<576, 256, SMEM_BYTES>>>(Wfh, Wfx, Wih, Wix, Wch, Wcx, Woh, Wox, Wy);
    fuse_kernel<<<512, 256>>>(c_prev, bf, bi, bc, bo, by, out);
}